// round 1
// baseline (speedup 1.0000x reference)
#include <cuda_runtime.h>
#include <cstdint>

#define Bb 64
#define Nn 1024
#define Cc 768
#define NHh 12
#define KDd 64
// qkv row for head h: q at h*129, k_d at h*129+1+d, v_d at h*129+65+d

// ---------------- scratch (device globals; no allocation allowed) ----------
__device__ float g_q[Bb * NHh * Nn];     // [b][h][n]
__device__ float g_w[Bb * NHh * Nn];     // softmax(q)*w_cv  [b][h][n]
__device__ float g_sig[Bb * NHh];        // sum of g_w over n
__device__ float g_t[Bb * NHh * Cc];     // [b][h][c]
__device__ float g_cv[Bb * Cc];          // [b][h*64+d]
__device__ float g_v[Bb * Nn * Cc];      // relu(v)*cv intermediate (row-major 65536x768)

// ---------------- K1: q = x @ Wq^T + bq, stored [b][h][n] ------------------
__global__ void __launch_bounds__(256) k1_qproj(const float* __restrict__ x,
                                                const float* __restrict__ wqkv,
                                                const float* __restrict__ bqkv) {
    __shared__ float sW[NHh][Cc];
    __shared__ float sB[NHh];
    int tid = threadIdx.x;
    for (int i = tid; i < NHh * Cc; i += 256) {
        int h = i / Cc, c = i % Cc;
        sW[h][c] = wqkv[(h * 129) * Cc + c];
    }
    if (tid < NHh) sB[tid] = bqkv[tid * 129];
    __syncthreads();

    int warp = tid >> 5, lane = tid & 31;
    int row0 = blockIdx.x * 128;
    for (int r = row0 + warp; r < row0 + 128; r += 8) {
        const float* xr = x + (size_t)r * Cc;
        float acc[NHh];
#pragma unroll
        for (int h = 0; h < NHh; h++) acc[h] = 0.f;
        for (int c = lane; c < Cc; c += 32) {
            float xv = xr[c];
#pragma unroll
            for (int h = 0; h < NHh; h++) acc[h] += xv * sW[h][c];
        }
#pragma unroll
        for (int h = 0; h < NHh; h++) {
#pragma unroll
            for (int off = 16; off; off >>= 1)
                acc[h] += __shfl_xor_sync(0xffffffffu, acc[h], off);
        }
        if (lane == 0) {
            int b = r >> 10, n = r & 1023;
#pragma unroll
            for (int h = 0; h < NHh; h++)
                g_q[((size_t)b * NHh + h) * Nn + n] = acc[h] + sB[h];
        }
    }
}

// ---------------- K2: softmax over n per (b,h); g_w = s * w_cv; g_sig ------
__global__ void __launch_bounds__(256) k2_softmax(const float* __restrict__ wcv) {
    int bh = blockIdx.x;
    int tid = threadIdx.x;
    const float* q = g_q + (size_t)bh * Nn;
    __shared__ float red[256];

    float v0[4];
    float m = -1e30f;
#pragma unroll
    for (int i = 0; i < 4; i++) { v0[i] = q[tid + 256 * i]; m = fmaxf(m, v0[i]); }
    red[tid] = m; __syncthreads();
    for (int s = 128; s; s >>= 1) { if (tid < s) red[tid] = fmaxf(red[tid], red[tid + s]); __syncthreads(); }
    m = red[0]; __syncthreads();

    float e[4]; float sum = 0.f;
#pragma unroll
    for (int i = 0; i < 4; i++) { e[i] = expf(v0[i] - m); sum += e[i]; }
    red[tid] = sum; __syncthreads();
    for (int s = 128; s; s >>= 1) { if (tid < s) red[tid] += red[tid + s]; __syncthreads(); }
    float inv = 1.f / red[0]; __syncthreads();

    float wsum = 0.f;
#pragma unroll
    for (int i = 0; i < 4; i++) {
        int n = tid + 256 * i;
        float wv = e[i] * inv * wcv[n];
        g_w[(size_t)bh * Nn + n] = wv;
        wsum += wv;
    }
    red[tid] = wsum; __syncthreads();
    for (int s = 128; s; s >>= 1) { if (tid < s) red[tid] += red[tid + s]; __syncthreads(); }
    if (tid == 0) g_sig[bh] = red[0];
}

// ---------------- K3: t[b][h][c] = sum_n g_w[b][h][n] * x[b][n][c] ---------
__global__ void __launch_bounds__(128) k3_t(const float* __restrict__ x) {
    int b = blockIdx.y;
    int c = blockIdx.x * 128 + threadIdx.x;
    __shared__ float sw[NHh * Nn];  // 48KB
    for (int i = threadIdx.x; i < NHh * Nn; i += 128)
        sw[i] = g_w[(size_t)b * NHh * Nn + i];
    __syncthreads();

    float acc[NHh];
#pragma unroll
    for (int h = 0; h < NHh; h++) acc[h] = 0.f;
    const float* xb = x + (size_t)b * Nn * Cc + c;
#pragma unroll 4
    for (int n = 0; n < Nn; n++) {
        float xv = xb[(size_t)n * Cc];
#pragma unroll
        for (int h = 0; h < NHh; h++) acc[h] += xv * sw[h * Nn + n];
    }
#pragma unroll
    for (int h = 0; h < NHh; h++)
        g_t[((size_t)b * NHh + h) * Cc + c] = acc[h];
}

// ---------------- K4: cv[b][h*64+d] = Wk[h,d,:] . t[b,h,:] + bk*sigma ------
__global__ void __launch_bounds__(64) k4_cv(const float* __restrict__ wqkv,
                                            const float* __restrict__ bqkv) {
    int b = blockIdx.x / NHh, h = blockIdx.x % NHh;
    int d = threadIdx.x;
    __shared__ float st[Cc];
    for (int i = d; i < Cc; i += 64) st[i] = g_t[((size_t)b * NHh + h) * Cc + i];
    __syncthreads();

    const float4* wr = (const float4*)(wqkv + (size_t)(h * 129 + 1 + d) * Cc);
    const float4* tr = (const float4*)st;
    float acc = 0.f;
#pragma unroll 4
    for (int i = 0; i < Cc / 4; i++) {
        float4 w4 = wr[i];
        float4 t4 = tr[i];
        acc += w4.x * t4.x + w4.y * t4.y + w4.z * t4.z + w4.w * t4.w;
    }
    g_cv[b * Cc + h * KDd + d] = acc + bqkv[h * 129 + 1 + d] * g_sig[b * NHh + h];
}

// ---------------- K5: tf32 mma GEMM, 128x128x32 tiles ----------------------
__device__ __forceinline__ uint32_t f2tf32(float f) {
    uint32_t r;
    asm("cvt.rna.tf32.f32 %0, %1;" : "=r"(r) : "f"(f));
    return r;
}

__device__ __forceinline__ void mma_tf32(float c[4], uint32_t a0, uint32_t a1,
                                         uint32_t a2, uint32_t a3,
                                         uint32_t b0, uint32_t b1) {
    asm volatile(
        "mma.sync.aligned.m16n8k8.row.col.f32.tf32.tf32.f32 "
        "{%0,%1,%2,%3}, {%4,%5,%6,%7}, {%8,%9}, {%0,%1,%2,%3};"
        : "+f"(c[0]), "+f"(c[1]), "+f"(c[2]), "+f"(c[3])
        : "r"(a0), "r"(a1), "r"(a2), "r"(a3), "r"(b0), "r"(b1));
}

// MODE 0: A = x, B = wqkv (v rows), epilogue relu(v+bv)*cv -> g_v
// MODE 1: A = g_v, B = w_out,       epilogue +b_out          -> out
template <int MODE>
__global__ void __launch_bounds__(256) k5_gemm(const float* __restrict__ Ag,
                                               const float* __restrict__ Bg,
                                               const float* __restrict__ bias,
                                               float* __restrict__ outg) {
    __shared__ uint32_t sA[128][36];
    __shared__ uint32_t sB[128][36];

    const int tid = threadIdx.x;
    const int warp = tid >> 5, lane = tid & 31;
    const int wm = warp >> 2, wn = warp & 3;   // 2x4 warp grid
    const int gid = lane >> 2, tg = lane & 3;
    const int bm = blockIdx.y, bn = blockIdx.x;
    const int arow0 = bm * 128;
    const int brow0 = bn * 128;

    const int ldr = tid >> 3;          // 0..31
    const int ldc = (tid & 7) * 4;     // 0..28

    const float* Aptr = (MODE == 0) ? Ag : g_v;
    float* Optr = (MODE == 0) ? g_v : outg;

    float acc[4][4][4];
#pragma unroll
    for (int mi = 0; mi < 4; mi++)
#pragma unroll
        for (int ni = 0; ni < 4; ni++)
#pragma unroll
            for (int rg = 0; rg < 4; rg++) acc[mi][ni][rg] = 0.f;

    // precompute B global rows for the 4 staged rows of this thread
    int browg[4];
#pragma unroll
    for (int i = 0; i < 4; i++) {
        int j = brow0 + ldr + i * 32;
        browg[i] = (MODE == 0) ? ((j >> 6) * 129 + 65 + (j & 63)) : j;
    }

    float4 ra[4], rb[4];
#pragma unroll
    for (int i = 0; i < 4; i++) {
        ra[i] = *(const float4*)(Aptr + (size_t)(arow0 + ldr + i * 32) * Cc + ldc);
        rb[i] = *(const float4*)(Bg + (size_t)browg[i] * Cc + ldc);
    }

    for (int k0 = 0; k0 < Cc; k0 += 32) {
        __syncthreads();
#pragma unroll
        for (int i = 0; i < 4; i++) {
            int r = ldr + i * 32;
            sA[r][ldc + 0] = f2tf32(ra[i].x);
            sA[r][ldc + 1] = f2tf32(ra[i].y);
            sA[r][ldc + 2] = f2tf32(ra[i].z);
            sA[r][ldc + 3] = f2tf32(ra[i].w);
            sB[r][ldc + 0] = f2tf32(rb[i].x);
            sB[r][ldc + 1] = f2tf32(rb[i].y);
            sB[r][ldc + 2] = f2tf32(rb[i].z);
            sB[r][ldc + 3] = f2tf32(rb[i].w);
        }
        __syncthreads();

        if (k0 + 32 < Cc) {
            int kn = k0 + 32;
#pragma unroll
            for (int i = 0; i < 4; i++) {
                ra[i] = *(const float4*)(Aptr + (size_t)(arow0 + ldr + i * 32) * Cc + kn + ldc);
                rb[i] = *(const float4*)(Bg + (size_t)browg[i] * Cc + kn + ldc);
            }
        }

#pragma unroll
        for (int ks = 0; ks < 4; ks++) {
            const int kk = ks * 8 + tg;
            uint32_t af[4][4];
            uint32_t bf[4][2];
#pragma unroll
            for (int mi = 0; mi < 4; mi++) {
                int r = wm * 64 + mi * 16 + gid;
                af[mi][0] = sA[r][kk];
                af[mi][1] = sA[r + 8][kk];
                af[mi][2] = sA[r][kk + 4];
                af[mi][3] = sA[r + 8][kk + 4];
            }
#pragma unroll
            for (int ni = 0; ni < 4; ni++) {
                int cB = wn * 32 + ni * 8 + gid;
                bf[ni][0] = sB[cB][kk];
                bf[ni][1] = sB[cB][kk + 4];
            }
#pragma unroll
            for (int mi = 0; mi < 4; mi++)
#pragma unroll
                for (int ni = 0; ni < 4; ni++)
                    mma_tf32(acc[mi][ni], af[mi][0], af[mi][1], af[mi][2], af[mi][3],
                             bf[ni][0], bf[ni][1]);
        }
    }

    // epilogue
#pragma unroll
    for (int mi = 0; mi < 4; mi++) {
#pragma unroll
        for (int ni = 0; ni < 4; ni++) {
#pragma unroll
            for (int rg = 0; rg < 4; rg++) {
                int row = arow0 + wm * 64 + mi * 16 + gid + ((rg >> 1) ? 8 : 0);
                int col = brow0 + wn * 32 + ni * 8 + tg * 2 + (rg & 1);
                float v = acc[mi][ni][rg];
                if (MODE == 0) {
                    float bv = bias[(col >> 6) * 129 + 65 + (col & 63)];
                    v = fmaxf(v + bv, 0.f) * g_cv[(row >> 10) * Cc + col];
                } else {
                    v = v + bias[col];
                }
                Optr[(size_t)row * Cc + col] = v;
            }
        }
    }
}

// ---------------- launch ---------------------------------------------------
extern "C" void kernel_launch(void* const* d_in, const int* in_sizes, int n_in,
                              void* d_out, int out_size) {
    const float* x = (const float*)d_in[0];
    const float* wqkv = (const float*)d_in[1];
    const float* bqkv = (const float*)d_in[2];
    const float* wcv = (const float*)d_in[3];
    const float* wout = (const float*)d_in[4];
    const float* bout = (const float*)d_in[5];
    float* out = (float*)d_out;

    k1_qproj<<<512, 256>>>(x, wqkv, bqkv);
    k2_softmax<<<Bb * NHh, 256>>>(wcv);
    k3_t<<<dim3(Cc / 128, Bb), 128>>>(x);
    k4_cv<<<Bb * NHh, 64>>>(wqkv, bqkv);
    k5_gemm<0><<<dim3(6, 512), 256>>>(x, wqkv, bqkv, nullptr);
    k5_gemm<1><<<dim3(6, 512), 256>>>(nullptr, wout, bout, out);
}

// round 2
// speedup vs baseline: 1.0384x; 1.0384x over previous
#include <cuda_runtime.h>
#include <cuda_bf16.h>
#include <cstdint>

#define Bb 64
#define Nn 1024
#define Cc 768
#define NHh 12
#define KDd 64
#define MROWS (Bb * Nn)

// ---------------- scratch ---------------------------------------------------
__device__ float g_q[Bb * NHh * Nn];
__device__ float g_w[Bb * NHh * Nn];
__device__ float g_sig[Bb * NHh];
__device__ float g_t[Bb * NHh * Cc];
__device__ float g_cv[Bb * Cc];
__device__ __nv_bfloat16 g_xb[(size_t)MROWS * Cc];   // x in bf16
__device__ __nv_bfloat16 g_vb[(size_t)MROWS * Cc];   // relu(v)*cv in bf16
__device__ __nv_bfloat16 g_wvb[Cc * Cc];             // v-weights, dense [o][c]
__device__ __nv_bfloat16 g_wob[Cc * Cc];             // w_out bf16

__device__ __forceinline__ uint32_t f2bf2(float lo, float hi) {
    uint32_t r;
    asm("cvt.rn.bf16x2.f32 %0, %1, %2;" : "=r"(r) : "f"(hi), "f"(lo));
    return r;
}

// ---------------- K0: weight conversion ------------------------------------
__global__ void __launch_bounds__(256) k0_wconv(const float* __restrict__ wqkv,
                                                const float* __restrict__ wout) {
    int o = blockIdx.x;               // 0..767
    int h = o >> 6, d = o & 63;
    const float2* s1 = (const float2*)(wqkv + (size_t)(h * 129 + 65 + d) * Cc);
    const float2* s2 = (const float2*)(wout + (size_t)o * Cc);
    uint32_t* d1 = (uint32_t*)g_wvb + o * (Cc / 2);
    uint32_t* d2 = (uint32_t*)g_wob + o * (Cc / 2);
    for (int i = threadIdx.x; i < Cc / 2; i += 256) {
        float2 a = s1[i]; d1[i] = f2bf2(a.x, a.y);
        float2 b = s2[i]; d2[i] = f2bf2(b.x, b.y);
    }
}

// ---------------- K1: q projection + x->bf16 --------------------------------
__global__ void __launch_bounds__(256) k1_qproj(const float* __restrict__ x,
                                                const float* __restrict__ wqkv,
                                                const float* __restrict__ bqkv) {
    __shared__ float sW[NHh][Cc];
    __shared__ float sB[NHh];
    int tid = threadIdx.x;
    for (int i = tid; i < NHh * Cc; i += 256) {
        int h = i / Cc, c = i % Cc;
        sW[h][c] = wqkv[(h * 129) * Cc + c];
    }
    if (tid < NHh) sB[tid] = bqkv[tid * 129];
    __syncthreads();

    int warp = tid >> 5, lane = tid & 31;
    int row0 = blockIdx.x * 128;
    for (int r = row0 + warp; r < row0 + 128; r += 8) {
        const float2* xr = (const float2*)(x + (size_t)r * Cc);
        uint32_t* xb = (uint32_t*)g_xb + (size_t)r * (Cc / 2);
        float acc[NHh];
#pragma unroll
        for (int h = 0; h < NHh; h++) acc[h] = 0.f;
#pragma unroll
        for (int i = 0; i < 12; i++) {
            int cp = lane + 32 * i;
            float2 xv = xr[cp];
            xb[cp] = f2bf2(xv.x, xv.y);
            int c = cp * 2;
#pragma unroll
            for (int h = 0; h < NHh; h++)
                acc[h] += xv.x * sW[h][c] + xv.y * sW[h][c + 1];
        }
#pragma unroll
        for (int h = 0; h < NHh; h++) {
#pragma unroll
            for (int off = 16; off; off >>= 1)
                acc[h] += __shfl_xor_sync(0xffffffffu, acc[h], off);
        }
        if (lane == 0) {
            int b = r >> 10, n = r & 1023;
#pragma unroll
            for (int h = 0; h < NHh; h++)
                g_q[((size_t)b * NHh + h) * Nn + n] = acc[h] + sB[h];
        }
    }
}

// ---------------- K2: softmax + *w_cv + sigma --------------------------------
__global__ void __launch_bounds__(256) k2_softmax(const float* __restrict__ wcv) {
    int bh = blockIdx.x;
    int tid = threadIdx.x;
    const float* q = g_q + (size_t)bh * Nn;
    __shared__ float red[256];

    float v0[4];
    float m = -1e30f;
#pragma unroll
    for (int i = 0; i < 4; i++) { v0[i] = q[tid + 256 * i]; m = fmaxf(m, v0[i]); }
    red[tid] = m; __syncthreads();
    for (int s = 128; s; s >>= 1) { if (tid < s) red[tid] = fmaxf(red[tid], red[tid + s]); __syncthreads(); }
    m = red[0]; __syncthreads();

    float e[4]; float sum = 0.f;
#pragma unroll
    for (int i = 0; i < 4; i++) { e[i] = expf(v0[i] - m); sum += e[i]; }
    red[tid] = sum; __syncthreads();
    for (int s = 128; s; s >>= 1) { if (tid < s) red[tid] += red[tid + s]; __syncthreads(); }
    float inv = 1.f / red[0]; __syncthreads();

    float wsum = 0.f;
#pragma unroll
    for (int i = 0; i < 4; i++) {
        int n = tid + 256 * i;
        float wv = e[i] * inv * wcv[n];
        g_w[(size_t)bh * Nn + n] = wv;
        wsum += wv;
    }
    red[tid] = wsum; __syncthreads();
    for (int s = 128; s; s >>= 1) { if (tid < s) red[tid] += red[tid + s]; __syncthreads(); }
    if (tid == 0) g_sig[bh] = red[0];
}

// ---------------- K3: t[b][h][c] = sum_n w[b][h][n]*x[b][n][c] (bf16 x) -----
__global__ void __launch_bounds__(128) k3_t() {
    int b = blockIdx.y;
    int cp = blockIdx.x * 128 + threadIdx.x;   // column pair 0..383
    __shared__ float sw[NHh * Nn];             // 48KB
    for (int i = threadIdx.x; i < NHh * Nn; i += 128)
        sw[i] = g_w[(size_t)b * NHh * Nn + i];
    __syncthreads();

    float acc0[NHh], acc1[NHh];
#pragma unroll
    for (int h = 0; h < NHh; h++) { acc0[h] = 0.f; acc1[h] = 0.f; }
    const uint32_t* xb = (const uint32_t*)g_xb + (size_t)b * Nn * (Cc / 2) + cp;
#pragma unroll 4
    for (int n = 0; n < Nn; n++) {
        uint32_t u = xb[(size_t)n * (Cc / 2)];
        float lo = __uint_as_float(u << 16);
        float hi = __uint_as_float(u & 0xffff0000u);
#pragma unroll
        for (int h = 0; h < NHh; h++) {
            float wv = sw[h * Nn + n];
            acc0[h] += lo * wv;
            acc1[h] += hi * wv;
        }
    }
#pragma unroll
    for (int h = 0; h < NHh; h++) {
        g_t[((size_t)b * NHh + h) * Cc + 2 * cp] = acc0[h];
        g_t[((size_t)b * NHh + h) * Cc + 2 * cp + 1] = acc1[h];
    }
}

// ---------------- K4: cv ----------------------------------------------------
__global__ void __launch_bounds__(256) k4_cv(const float* __restrict__ wqkv,
                                             const float* __restrict__ bqkv) {
    int b = blockIdx.x;
    __shared__ float st[NHh * Cc];             // 36KB
    for (int i = threadIdx.x; i < NHh * Cc; i += 256)
        st[i] = g_t[(size_t)b * NHh * Cc + i];
    __syncthreads();

    int tid = threadIdx.x;
    int i0 = tid, i1 = tid + 256, i2 = tid + 512;
    int h0 = i0 >> 6, d0 = i0 & 63;
    int h1 = i1 >> 6, d1 = i1 & 63;
    int h2 = i2 >> 6, d2 = i2 & 63;
    const float4* w0 = (const float4*)(wqkv + (size_t)(h0 * 129 + 1 + d0) * Cc);
    const float4* w1 = (const float4*)(wqkv + (size_t)(h1 * 129 + 1 + d1) * Cc);
    const float4* w2 = (const float4*)(wqkv + (size_t)(h2 * 129 + 1 + d2) * Cc);
    const float4* t0 = (const float4*)(st + h0 * Cc);
    const float4* t1 = (const float4*)(st + h1 * Cc);
    const float4* t2 = (const float4*)(st + h2 * Cc);
    float a0 = 0.f, a1 = 0.f, a2 = 0.f;
#pragma unroll 4
    for (int i = 0; i < Cc / 4; i++) {
        float4 wa = w0[i], ta = t0[i];
        a0 += wa.x * ta.x + wa.y * ta.y + wa.z * ta.z + wa.w * ta.w;
        float4 wb = w1[i], tb = t1[i];
        a1 += wb.x * tb.x + wb.y * tb.y + wb.z * tb.z + wb.w * tb.w;
        float4 wc = w2[i], tc = t2[i];
        a2 += wc.x * tc.x + wc.y * tc.y + wc.z * tc.z + wc.w * tc.w;
    }
    g_cv[b * Cc + i0] = a0 + bqkv[h0 * 129 + 1 + d0] * g_sig[b * NHh + h0];
    g_cv[b * Cc + i1] = a1 + bqkv[h1 * 129 + 1 + d1] * g_sig[b * NHh + h1];
    g_cv[b * Cc + i2] = a2 + bqkv[h2 * 129 + 1 + d2] * g_sig[b * NHh + h2];
}

// ---------------- K5: bf16 mma GEMM, 128x128x32 tiles -----------------------
__device__ __forceinline__ void mma_bf16(float c[4], const uint32_t a[4],
                                         const uint32_t b[2]) {
    asm volatile(
        "mma.sync.aligned.m16n8k16.row.col.f32.bf16.bf16.f32 "
        "{%0,%1,%2,%3}, {%4,%5,%6,%7}, {%8,%9}, {%0,%1,%2,%3};"
        : "+f"(c[0]), "+f"(c[1]), "+f"(c[2]), "+f"(c[3])
        : "r"(a[0]), "r"(a[1]), "r"(a[2]), "r"(a[3]), "r"(b[0]), "r"(b[1]));
}

// MODE 0: A=g_xb, B=g_wvb, epilogue relu(v+bv)*cv -> g_vb (bf16)
// MODE 1: A=g_vb, B=g_wob, epilogue +b_out        -> out  (fp32)
template <int MODE>
__global__ void __launch_bounds__(256) k5_gemm(const float* __restrict__ bias,
                                               float* __restrict__ outg) {
    __shared__ uint32_t sA[128][20];   // bf16 pairs, 16 used cols + 4 pad
    __shared__ uint32_t sB[128][20];

    const int tid = threadIdx.x;
    const int warp = tid >> 5, lane = tid & 31;
    const int wm = warp >> 2, wn = warp & 3;
    const int gid = lane >> 2, tg = lane & 3;
    const int arow0 = blockIdx.y * 128;
    const int brow0 = blockIdx.x * 128;

    const int ldr = tid >> 3;          // 0..31
    const int ldk = tid & 7;           // uint2 index within 32-k tile
    const int ldk2 = ldk * 2;          // uint32 col in smem

    const __nv_bfloat16* Ab = (MODE == 0) ? g_xb : g_vb;
    const __nv_bfloat16* Bm = (MODE == 0) ? g_wvb : g_wob;

    const uint2* Arow[4];
    const uint2* Brow[4];
#pragma unroll
    for (int i = 0; i < 4; i++) {
        Arow[i] = (const uint2*)(Ab + (size_t)(arow0 + ldr + 32 * i) * Cc);
        Brow[i] = (const uint2*)(Bm + (size_t)(brow0 + ldr + 32 * i) * Cc);
    }

    float acc[4][4][4];
#pragma unroll
    for (int mi = 0; mi < 4; mi++)
#pragma unroll
        for (int ni = 0; ni < 4; ni++)
#pragma unroll
            for (int rg = 0; rg < 4; rg++) acc[mi][ni][rg] = 0.f;

    uint2 ra[4], rb[4];
#pragma unroll
    for (int i = 0; i < 4; i++) {
        ra[i] = Arow[i][ldk];
        rb[i] = Brow[i][ldk];
    }

    for (int k0 = 0; k0 < Cc; k0 += 32) {
        __syncthreads();
#pragma unroll
        for (int i = 0; i < 4; i++) {
            int r = ldr + 32 * i;
            sA[r][ldk2] = ra[i].x; sA[r][ldk2 + 1] = ra[i].y;
            sB[r][ldk2] = rb[i].x; sB[r][ldk2 + 1] = rb[i].y;
        }
        __syncthreads();

        if (k0 + 32 < Cc) {
            int idx = (k0 + 32) / 4 + ldk;
#pragma unroll
            for (int i = 0; i < 4; i++) {
                ra[i] = Arow[i][idx];
                rb[i] = Brow[i][idx];
            }
        }

#pragma unroll
        for (int ks = 0; ks < 2; ks++) {
            const int kb = ks * 8;
            uint32_t af[4][4];
            uint32_t bfr[4][2];
#pragma unroll
            for (int mi = 0; mi < 4; mi++) {
                int r = wm * 64 + mi * 16 + gid;
                af[mi][0] = sA[r][kb + tg];
                af[mi][1] = sA[r + 8][kb + tg];
                af[mi][2] = sA[r][kb + tg + 4];
                af[mi][3] = sA[r + 8][kb + tg + 4];
            }
#pragma unroll
            for (int ni = 0; ni < 4; ni++) {
                int cB = wn * 32 + ni * 8 + gid;
                bfr[ni][0] = sB[cB][kb + tg];
                bfr[ni][1] = sB[cB][kb + tg + 4];
            }
#pragma unroll
            for (int mi = 0; mi < 4; mi++)
#pragma unroll
                for (int ni = 0; ni < 4; ni++)
                    mma_bf16(acc[mi][ni], af[mi], bfr[ni]);
        }
    }

    // epilogue
#pragma unroll
    for (int mi = 0; mi < 4; mi++) {
        int row = arow0 + wm * 64 + mi * 16 + gid;
#pragma unroll
        for (int ni = 0; ni < 4; ni++) {
            int col = brow0 + wn * 32 + ni * 8 + tg * 2;
            if (MODE == 0) {
                int hb = (col >> 6) * 129 + 65 + (col & 63);
                float bv0 = bias[hb], bv1 = bias[hb + 1];
                int b = row >> 10;
                float cv0 = g_cv[b * Cc + col], cv1 = g_cv[b * Cc + col + 1];
                float v00 = fmaxf(acc[mi][ni][0] + bv0, 0.f) * cv0;
                float v01 = fmaxf(acc[mi][ni][1] + bv1, 0.f) * cv1;
                float v10 = fmaxf(acc[mi][ni][2] + bv0, 0.f) * cv0;
                float v11 = fmaxf(acc[mi][ni][3] + bv1, 0.f) * cv1;
                uint32_t* dst = (uint32_t*)g_vb;
                dst[(size_t)row * (Cc / 2) + col / 2] = f2bf2(v00, v01);
                dst[(size_t)(row + 8) * (Cc / 2) + col / 2] = f2bf2(v10, v11);
            } else {
                float b0 = bias[col], b1 = bias[col + 1];
                float2 o0 = make_float2(acc[mi][ni][0] + b0, acc[mi][ni][1] + b1);
                float2 o1 = make_float2(acc[mi][ni][2] + b0, acc[mi][ni][3] + b1);
                *(float2*)(outg + (size_t)row * Cc + col) = o0;
                *(float2*)(outg + (size_t)(row + 8) * Cc + col) = o1;
            }
        }
    }
}

// ---------------- launch ----------------------------------------------------
extern "C" void kernel_launch(void* const* d_in, const int* in_sizes, int n_in,
                              void* d_out, int out_size) {
    const float* x = (const float*)d_in[0];
    const float* wqkv = (const float*)d_in[1];
    const float* bqkv = (const float*)d_in[2];
    const float* wcv = (const float*)d_in[3];
    const float* wout = (const float*)d_in[4];
    const float* bout = (const float*)d_in[5];
    float* out = (float*)d_out;

    k0_wconv<<<Cc, 256>>>(wqkv, wout);
    k1_qproj<<<512, 256>>>(x, wqkv, bqkv);
    k2_softmax<<<Bb * NHh, 256>>>(wcv);
    k3_t<<<dim3(3, Bb), 128>>>();
    k4_cv<<<Bb, 256>>>(wqkv, bqkv);
    k5_gemm<0><<<dim3(6, 512), 256>>>(bqkv, nullptr);
    k5_gemm<1><<<dim3(6, 512), 256>>>(bout, out);
}

// round 4
// speedup vs baseline: 1.4251x; 1.3724x over previous
#include <cuda_runtime.h>
#include <cuda_bf16.h>
#include <cstdint>

#define Bb 64
#define Nn 1024
#define Cc 768
#define NHh 12
#define KDd 64
#define MROWS (Bb * Nn)

// ---------------- scratch ---------------------------------------------------
__device__ float g_q[Bb * NHh * Nn];
__device__ float g_w[Bb * NHh * Nn];
__device__ float g_sig[Bb * NHh];
__device__ float g_tp[Bb * 8 * NHh * Cc];
__device__ float g_cv[Bb * Cc];
__device__ __align__(16) __nv_bfloat16 g_xb[(size_t)MROWS * Cc];
__device__ __align__(16) __nv_bfloat16 g_vb[(size_t)MROWS * Cc];
__device__ __align__(16) __nv_bfloat16 g_wvb[Cc * Cc];
__device__ __align__(16) __nv_bfloat16 g_wob[Cc * Cc];

__device__ __forceinline__ uint32_t f2bf2(float lo, float hi) {
    uint32_t r;
    asm("cvt.rn.bf16x2.f32 %0, %1, %2;" : "=r"(r) : "f"(hi), "f"(lo));
    return r;
}
__device__ __forceinline__ uint32_t smem_u32(const void* p) {
    uint32_t a;
    asm("{ .reg .u64 t; cvta.to.shared.u64 t, %1; cvt.u32.u64 %0, t; }" : "=r"(a) : "l"(p));
    return a;
}
__device__ __forceinline__ void cp16(uint32_t s, const void* g) {
    asm volatile("cp.async.cg.shared.global [%0], [%1], 16;" :: "r"(s), "l"(g));
}
#define CP_COMMIT() asm volatile("cp.async.commit_group;" ::: "memory")
#define CP_WAIT2() asm volatile("cp.async.wait_group 2;" ::: "memory")

__device__ __forceinline__ void ldsm4(uint32_t& r0, uint32_t& r1, uint32_t& r2,
                                      uint32_t& r3, uint32_t a) {
    asm volatile("ldmatrix.sync.aligned.m8n8.x4.shared.b16 {%0,%1,%2,%3}, [%4];"
                 : "=r"(r0), "=r"(r1), "=r"(r2), "=r"(r3) : "r"(a));
}
__device__ __forceinline__ void mma_bf16(float c[4], const uint32_t a[4],
                                         const uint32_t b0, const uint32_t b1) {
    asm volatile(
        "mma.sync.aligned.m16n8k16.row.col.f32.bf16.bf16.f32 "
        "{%0,%1,%2,%3}, {%4,%5,%6,%7}, {%8,%9}, {%0,%1,%2,%3};"
        : "+f"(c[0]), "+f"(c[1]), "+f"(c[2]), "+f"(c[3])
        : "r"(a[0]), "r"(a[1]), "r"(a[2]), "r"(a[3]), "r"(b0), "r"(b1));
}

// ---------------- K0: weight conversion ------------------------------------
__global__ void __launch_bounds__(256) k0_wconv(const float* __restrict__ wqkv,
                                                const float* __restrict__ wout) {
    int o = blockIdx.x;
    int h = o >> 6, d = o & 63;
    const float2* s1 = (const float2*)(wqkv + (size_t)(h * 129 + 65 + d) * Cc);
    const float2* s2 = (const float2*)(wout + (size_t)o * Cc);
    uint32_t* d1 = (uint32_t*)g_wvb + o * (Cc / 2);
    uint32_t* d2 = (uint32_t*)g_wob + o * (Cc / 2);
    for (int i = threadIdx.x; i < Cc / 2; i += 256) {
        float2 a = s1[i]; d1[i] = f2bf2(a.x, a.y);
        float2 b = s2[i]; d2[i] = f2bf2(b.x, b.y);
    }
}

// ---------------- K1: q projection + x->bf16 --------------------------------
__global__ void __launch_bounds__(256) k1_qproj(const float* __restrict__ x,
                                                const float* __restrict__ wqkv,
                                                const float* __restrict__ bqkv) {
    __shared__ float sW[NHh][Cc];
    __shared__ float sB[NHh];
    int tid = threadIdx.x;
    for (int i = tid; i < NHh * Cc; i += 256) {
        int h = i / Cc, c = i % Cc;
        sW[h][c] = wqkv[(h * 129) * Cc + c];
    }
    if (tid < NHh) sB[tid] = bqkv[tid * 129];
    __syncthreads();

    int warp = tid >> 5, lane = tid & 31;
    int row0 = blockIdx.x * 128;
    for (int r = row0 + warp; r < row0 + 128; r += 8) {
        const float2* xr = (const float2*)(x + (size_t)r * Cc);
        uint32_t* xb = (uint32_t*)g_xb + (size_t)r * (Cc / 2);
        float acc[NHh];
#pragma unroll
        for (int h = 0; h < NHh; h++) acc[h] = 0.f;
#pragma unroll
        for (int i = 0; i < 12; i++) {
            int cp = lane + 32 * i;
            float2 xv = xr[cp];
            xb[cp] = f2bf2(xv.x, xv.y);
            int c = cp * 2;
#pragma unroll
            for (int h = 0; h < NHh; h++)
                acc[h] += xv.x * sW[h][c] + xv.y * sW[h][c + 1];
        }
#pragma unroll
        for (int h = 0; h < NHh; h++) {
#pragma unroll
            for (int off = 16; off; off >>= 1)
                acc[h] += __shfl_xor_sync(0xffffffffu, acc[h], off);
        }
        if (lane == 0) {
            int b = r >> 10, n = r & 1023;
#pragma unroll
            for (int h = 0; h < NHh; h++)
                g_q[((size_t)b * NHh + h) * Nn + n] = acc[h] + sB[h];
        }
    }
}

// ---------------- K2: softmax + *w_cv + sigma -------------------------------
__global__ void __launch_bounds__(256) k2_softmax(const float* __restrict__ wcv) {
    int bh = blockIdx.x;
    int tid = threadIdx.x;
    const float* q = g_q + (size_t)bh * Nn;
    __shared__ float red[256];

    float v0[4];
    float m = -1e30f;
#pragma unroll
    for (int i = 0; i < 4; i++) { v0[i] = q[tid + 256 * i]; m = fmaxf(m, v0[i]); }
    red[tid] = m; __syncthreads();
    for (int s = 128; s; s >>= 1) { if (tid < s) red[tid] = fmaxf(red[tid], red[tid + s]); __syncthreads(); }
    m = red[0]; __syncthreads();

    float e[4]; float sum = 0.f;
#pragma unroll
    for (int i = 0; i < 4; i++) { e[i] = expf(v0[i] - m); sum += e[i]; }
    red[tid] = sum; __syncthreads();
    for (int s = 128; s; s >>= 1) { if (tid < s) red[tid] += red[tid + s]; __syncthreads(); }
    float inv = 1.f / red[0]; __syncthreads();

    float wsum = 0.f;
#pragma unroll
    for (int i = 0; i < 4; i++) {
        int n = tid + 256 * i;
        float wv = e[i] * inv * wcv[n];
        g_w[(size_t)bh * Nn + n] = wv;
        wsum += wv;
    }
    red[tid] = wsum; __syncthreads();
    for (int s = 128; s; s >>= 1) { if (tid < s) red[tid] += red[tid + s]; __syncthreads(); }
    if (tid == 0) g_sig[bh] = red[0];
}

// ---------------- K3: t partials over 8 n-chunks ----------------------------
__global__ void __launch_bounds__(128) k3_t() {
    int b = blockIdx.y;
    int ch = blockIdx.z;
    int cp = blockIdx.x * 128 + threadIdx.x;
    __shared__ float sw[NHh * 128];
    for (int h = 0; h < NHh; h++)
        sw[h * 128 + threadIdx.x] = g_w[((size_t)b * NHh + h) * Nn + ch * 128 + threadIdx.x];
    __syncthreads();

    float acc0[NHh], acc1[NHh];
#pragma unroll
    for (int h = 0; h < NHh; h++) { acc0[h] = 0.f; acc1[h] = 0.f; }
    const uint32_t* xb = (const uint32_t*)g_xb + ((size_t)b * Nn + ch * 128) * (Cc / 2) + cp;
#pragma unroll 4
    for (int n = 0; n < 128; n++) {
        uint32_t u = xb[(size_t)n * (Cc / 2)];
        float lo = __uint_as_float(u << 16);
        float hi = __uint_as_float(u & 0xffff0000u);
#pragma unroll
        for (int h = 0; h < NHh; h++) {
            float wv = sw[h * 128 + n];
            acc0[h] += lo * wv;
            acc1[h] += hi * wv;
        }
    }
    float* tp = g_tp + ((size_t)(b * 8 + ch) * NHh) * Cc;
#pragma unroll
    for (int h = 0; h < NHh; h++) {
        tp[h * Cc + 2 * cp] = acc0[h];
        tp[h * Cc + 2 * cp + 1] = acc1[h];
    }
}

// ---------------- K4: cv ----------------------------------------------------
__global__ void __launch_bounds__(256) k4_cv(const float* __restrict__ wqkv,
                                             const float* __restrict__ bqkv) {
    int b = blockIdx.x;
    __shared__ float st[NHh * Cc];
    for (int i = threadIdx.x; i < NHh * Cc; i += 256) {
        float s = 0.f;
#pragma unroll
        for (int ch = 0; ch < 8; ch++)
            s += g_tp[((size_t)(b * 8 + ch) * NHh) * Cc + i];
        st[i] = s;
    }
    __syncthreads();

    int tid = threadIdx.x;
    int i0 = tid, i1 = tid + 256, i2 = tid + 512;
    int h0 = i0 >> 6, d0 = i0 & 63;
    int h1 = i1 >> 6, d1 = i1 & 63;
    int h2 = i2 >> 6, d2 = i2 & 63;
    const float4* w0 = (const float4*)(wqkv + (size_t)(h0 * 129 + 1 + d0) * Cc);
    const float4* w1 = (const float4*)(wqkv + (size_t)(h1 * 129 + 1 + d1) * Cc);
    const float4* w2 = (const float4*)(wqkv + (size_t)(h2 * 129 + 1 + d2) * Cc);
    const float4* t0 = (const float4*)(st + h0 * Cc);
    const float4* t1 = (const float4*)(st + h1 * Cc);
    const float4* t2 = (const float4*)(st + h2 * Cc);
    float a0 = 0.f, a1 = 0.f, a2 = 0.f;
#pragma unroll 4
    for (int i = 0; i < Cc / 4; i++) {
        float4 wa = w0[i], ta = t0[i];
        a0 += wa.x * ta.x + wa.y * ta.y + wa.z * ta.z + wa.w * ta.w;
        float4 wb = w1[i], tb = t1[i];
        a1 += wb.x * tb.x + wb.y * tb.y + wb.z * tb.z + wb.w * tb.w;
        float4 wc = w2[i], tc = t2[i];
        a2 += wc.x * tc.x + wc.y * tc.y + wc.z * tc.z + wc.w * tc.w;
    }
    g_cv[b * Cc + i0] = a0 + bqkv[h0 * 129 + 1 + d0] * g_sig[b * NHh + h0];
    g_cv[b * Cc + i1] = a1 + bqkv[h1 * 129 + 1 + d1] * g_sig[b * NHh + h1];
    g_cv[b * Cc + i2] = a2 + bqkv[h2 * 129 + 1 + d2] * g_sig[b * NHh + h2];
}

// ---------------- K5: bf16 HMMA GEMM, 128x128x64 tiles, cp.async x3 --------
// MODE 0: A=g_xb, B=g_wvb, epilogue relu(v+bv)*cv -> g_vb (bf16)
// MODE 1: A=g_vb, B=g_wob, epilogue +b_out        -> out  (fp32)
#define K5_STAGES 3
#define K5_STAGE_BYTES 32768
#define K5_SMEM (K5_STAGES * K5_STAGE_BYTES)

template <int MODE>
__global__ void __launch_bounds__(256, 2) k5_gemm(const float* __restrict__ bias,
                                                  float* __restrict__ outg) {
    extern __shared__ char smem[];
    const uint32_t tb = smem_u32(smem);

    const int tid = threadIdx.x;
    const int warp = tid >> 5, lane = tid & 31;
    const int wm = warp >> 2, wn = warp & 3;
    const int gid = lane >> 2, tg = lane & 3;
    const int arow0 = blockIdx.y * 128;
    const int brow0 = blockIdx.x * 128;

    const __nv_bfloat16* Ab = (MODE == 0) ? g_xb : g_vb;
    const __nv_bfloat16* Bm = (MODE == 0) ? g_wvb : g_wob;
    const uint4* Ag4 = (const uint4*)Ab;
    const uint4* Bg4 = (const uint4*)Bm;

    // per-thread cp.async slots: 4 chunks A + 4 chunks B per stage
    int rowq[4], jjq[4];
    uint32_t swo[4];
    size_t aBase[4], bBase[4];
#pragma unroll
    for (int i = 0; i < 4; i++) {
        int q = tid + 256 * i;
        rowq[i] = q >> 3;
        jjq[i] = q & 7;
        swo[i] = (uint32_t)(rowq[i] * 128 + ((jjq[i] ^ (rowq[i] & 7)) * 16));
        aBase[i] = (size_t)(arow0 + rowq[i]) * 96 + jjq[i];
        bBase[i] = (size_t)(brow0 + rowq[i]) * 96 + jjq[i];
    }

    auto load_stage = [&](int kc, int s) {
        uint32_t aT = tb + s * K5_STAGE_BYTES;
        uint32_t bT = aT + 16384;
        size_t koff = (size_t)kc * 8;
#pragma unroll
        for (int i = 0; i < 4; i++) {
            cp16(aT + swo[i], Ag4 + aBase[i] + koff);
            cp16(bT + swo[i], Bg4 + bBase[i] + koff);
        }
    };

    // ldmatrix address prep
    const int seg = lane >> 3, l7 = lane & 7;
    uint32_t aRow[4], bRow[2];
    int kselA = seg >> 1, kselB = seg & 1;
#pragma unroll
    for (int mi = 0; mi < 4; mi++)
        aRow[mi] = (uint32_t)(wm * 64 + mi * 16 + (seg & 1) * 8 + l7);
#pragma unroll
    for (int n2 = 0; n2 < 2; n2++)
        bRow[n2] = (uint32_t)(wn * 32 + n2 * 16 + (seg >> 1) * 8 + l7);

    float acc[4][4][4];
#pragma unroll
    for (int mi = 0; mi < 4; mi++)
#pragma unroll
        for (int ni = 0; ni < 4; ni++)
#pragma unroll
            for (int rg = 0; rg < 4; rg++) acc[mi][ni][rg] = 0.f;

    load_stage(0, 0); CP_COMMIT();
    load_stage(1, 1); CP_COMMIT();

#pragma unroll 1
    for (int kc = 0; kc < 12; kc++) {
        if (kc + 2 < 12) load_stage(kc + 2, (kc + 2) % K5_STAGES);
        CP_COMMIT();
        CP_WAIT2();
        __syncthreads();

        const int s = kc % K5_STAGES;
        const uint32_t aT = tb + s * K5_STAGE_BYTES;
        const uint32_t bT = aT + 16384;

#pragma unroll
        for (int ks = 0; ks < 4; ks++) {
            uint32_t af[4][4];
            uint32_t bf[2][4];
#pragma unroll
            for (int mi = 0; mi < 4; mi++) {
                uint32_t addr = aT + aRow[mi] * 128 +
                                (((uint32_t)(ks * 2 + kselA) ^ (aRow[mi] & 7)) * 16);
                ldsm4(af[mi][0], af[mi][1], af[mi][2], af[mi][3], addr);
            }
#pragma unroll
            for (int n2 = 0; n2 < 2; n2++) {
                uint32_t addr = bT + bRow[n2] * 128 +
                                (((uint32_t)(ks * 2 + kselB) ^ (bRow[n2] & 7)) * 16);
                ldsm4(bf[n2][0], bf[n2][1], bf[n2][2], bf[n2][3], addr);
            }
#pragma unroll
            for (int mi = 0; mi < 4; mi++) {
#pragma unroll
                for (int n2 = 0; n2 < 2; n2++) {
                    mma_bf16(acc[mi][2 * n2], af[mi], bf[n2][0], bf[n2][1]);
                    mma_bf16(acc[mi][2 * n2 + 1], af[mi], bf[n2][2], bf[n2][3]);
                }
            }
        }
        __syncthreads();
    }

    // epilogue
#pragma unroll
    for (int mi = 0; mi < 4; mi++) {
        int row = arow0 + wm * 64 + mi * 16 + gid;
#pragma unroll
        for (int ni = 0; ni < 4; ni++) {
            int col = brow0 + wn * 32 + ni * 8 + tg * 2;
            if (MODE == 0) {
                int hb = (col >> 6) * 129 + 65 + (col & 63);
                float bv0 = bias[hb], bv1 = bias[hb + 1];
                int b = row >> 10;
                float cv0 = g_cv[b * Cc + col], cv1 = g_cv[b * Cc + col + 1];
                float v00 = fmaxf(acc[mi][ni][0] + bv0, 0.f) * cv0;
                float v01 = fmaxf(acc[mi][ni][1] + bv1, 0.f) * cv1;
                float v10 = fmaxf(acc[mi][ni][2] + bv0, 0.f) * cv0;
                float v11 = fmaxf(acc[mi][ni][3] + bv1, 0.f) * cv1;
                uint32_t* dst = (uint32_t*)g_vb;
                dst[(size_t)row * (Cc / 2) + col / 2] = f2bf2(v00, v01);
                dst[(size_t)(row + 8) * (Cc / 2) + col / 2] = f2bf2(v10, v11);
            } else {
                float b0 = bias[col], b1 = bias[col + 1];
                *(float2*)(outg + (size_t)row * Cc + col) =
                    make_float2(acc[mi][ni][0] + b0, acc[mi][ni][1] + b1);
                *(float2*)(outg + (size_t)(row + 8) * Cc + col) =
                    make_float2(acc[mi][ni][2] + b0, acc[mi][ni][3] + b1);
            }
        }
    }
}

// ---------------- launch ----------------------------------------------------
extern "C" void kernel_launch(void* const* d_in, const int* in_sizes, int n_in,
                              void* d_out, int out_size) {
    const float* x = (const float*)d_in[0];
    const float* wqkv = (const float*)d_in[1];
    const float* bqkv = (const float*)d_in[2];
    const float* wcv = (const float*)d_in[3];
    const float* wout = (const float*)d_in[4];
    const float* bout = (const float*)d_in[5];
    float* out = (float*)d_out;

    cudaFuncSetAttribute(k5_gemm<0>, cudaFuncAttributeMaxDynamicSharedMemorySize, K5_SMEM);
    cudaFuncSetAttribute(k5_gemm<1>, cudaFuncAttributeMaxDynamicSharedMemorySize, K5_SMEM);

    k0_wconv<<<Cc, 256>>>(wqkv, wout);
    k1_qproj<<<512, 256>>>(x, wqkv, bqkv);
    k2_softmax<<<Bb * NHh, 256>>>(wcv);
    k3_t<<<dim3(3, Bb, 8), 128>>>();
    k4_cv<<<Bb, 256>>>(wqkv, bqkv);
    k5_gemm<0><<<dim3(6, 512), 256, K5_SMEM>>>(bqkv, nullptr);
    k5_gemm<1><<<dim3(6, 512), 256, K5_SMEM>>>(bout, out);
}